// round 15
// baseline (speedup 1.0000x reference)
#include <cuda_runtime.h>
#include <math.h>

#define NN    512
#define BIT   64
#define NCLS  100
#define ALPHA 5.0f
#define LAM   1.0f
#define RPB   2                 // anchor rows per block
#define NB    (NN / RPB)        // 256 blocks
#define NT    512               // threads per block (16 warps)

// Scratch (allocation-free: __device__ globals)
__device__ float4 g_part[NB];    // {bsum, bcnt, bl2, 0} per block
__device__ unsigned int g_done = 0;

// ---------------------------------------------------------------------------
// Single fused kernel: 256 blocks x 512 threads. R15: scan-warp compaction
// prefix (kills the per-thread popc loops), clamp-free softplus (bitwise
// identical in range), warp-only barrier-free final tail.
// ---------------------------------------------------------------------------
__global__ void __launch_bounds__(NT) fused_kernel(const float* __restrict__ u,
                                                   const float* __restrict__ y,
                                                   float* __restrict__ out) {
    __shared__ float4 s_ur[RPB][BIT / 4];          // anchor rows of u     (512 B)
    __shared__ float4 s_pp[RPB][NN];               // quarter partials     (16 KB)
    __shared__ float  s_ip[RPB][NN];               // ip rows              (4 KB)
    __shared__ int    s_lbl[RPB];
    __shared__ unsigned s_gmask[RPB][16];          // pos bitmask words
    __shared__ int    s_gpre[RPB][16];             // exclusive prefix of popc
    __shared__ int    s_npos[RPB];
    __shared__ short  s_poslist[RPB][NN];          // positive indices     (2 KB)
    __shared__ float  s_part[RPB][16];             // per-warp pair partials
    __shared__ float  s_s2[4];                     // loss2 partials
    __shared__ int    s_islast;

    const int tid  = threadIdx.x;
    const int bid  = blockIdx.x;
    const int r0   = bid * RPB;
    const int lane = tid & 31;
    const int wrp  = tid >> 5;                     // 0..15

    // --- phase 0: anchor rows of u into smem + label recovery (one-hot) ---
    if (tid < RPB * (BIT / 4)) {                   // 32 float4 loads
        int i = tid >> 4;
        int k = tid & 15;
        s_ur[i][k] = ((const float4*)(u + (size_t)(r0 + i) * BIT))[k];
    }
    if (tid < RPB * NCLS) {                        // 200 <= 512, one writer/row
        int i = tid / NCLS;
        int c = tid % NCLS;
        if (y[(size_t)(r0 + i) * NCLS + c] > 0.5f) s_lbl[i] = c;
    }
    __syncthreads();                               // barrier 1

    const int lbl0 = s_lbl[0];
    const int lbl1 = s_lbl[1];

    // --- scattered isneg gathers issued EARLY; hide under the dot loop ---
    const float yv0 = __ldg(y + (size_t)tid * NCLS + lbl0);   // row0, j = tid
    const float yv1 = __ldg(y + (size_t)tid * NCLS + lbl1);   // row1, j = tid

    // --- coalesced dot phase: 32 rows / iter, 2 anchors, 2-level shuffle ---
    {
        const float4 av0 = s_ur[0][tid & 15];
        const float4 av1 = s_ur[1][tid & 15];
        const int row_in_iter = tid >> 4;          // 0..31
        const int q = (lane >> 2) & 3;             // quarter within row
        const bool writer = ((lane & 3) == 0);
        #pragma unroll 8
        for (int it = 0; it < NN / 32; ++it) {     // 16 iterations
            float4 b = ((const float4*)u)[it * (32 * BIT / 4) + tid];
            float p0 = av0.x * b.x + av0.y * b.y + av0.z * b.z + av0.w * b.w;
            float p1 = av1.x * b.x + av1.y * b.y + av1.z * b.z + av1.w * b.w;
            p0 += __shfl_xor_sync(0xffffffffu, p0, 1);
            p0 += __shfl_xor_sync(0xffffffffu, p0, 2);
            p1 += __shfl_xor_sync(0xffffffffu, p1, 1);
            p1 += __shfl_xor_sync(0xffffffffu, p1, 2);
            if (writer) {
                int row = it * 32 + row_in_iter;
                ((float*)&s_pp[0][row])[q] = p0;
                ((float*)&s_pp[1][row])[q] = p1;
            }
        }
    }

    // --- isneg in registers; ballots (full word kept in registers) ---
    const bool n0 = (yv0 == 0.0f);                 // true = negative pair
    const bool n1 = (yv1 == 0.0f);
    const unsigned m0 = __ballot_sync(0xffffffffu, !n0);   // positives row0
    const unsigned m1 = __ballot_sync(0xffffffffu, !n1);   // positives row1
    if (lane == 0) {
        s_gmask[0][wrp] = m0;
        s_gmask[1][wrp] = m1;
    }

    // --- loss2 partial: this block's RPB*BIT = 128 u values (smem copy) ---
    if (tid < RPB * BIT) {
        float v  = ((const float*)s_ur)[tid];
        float sg = (v > 0.0f) ? 1.0f : ((v < 0.0f) ? -1.0f : 0.0f);
        float d  = v - sg;
        float s2 = d * d;
        #pragma unroll
        for (int o = 16; o > 0; o >>= 1) s2 += __shfl_xor_sync(0xffffffffu, s2, o);
        if (lane == 0) s_s2[wrp] = s2;
    }
    __syncthreads();                               // barrier 2

    // --- scan warps (0,1): exclusive prefix of popcounts over 16 words ---
    if (wrp < RPB) {
        const int row = wrp;
        int pc = (lane < 16) ? __popc(s_gmask[row][lane]) : 0;
        int scan = pc;
        #pragma unroll
        for (int o = 1; o < 16; o <<= 1) {
            int v = __shfl_up_sync(0xffffffffu, scan, o);
            if (lane >= o) scan += v;
        }
        if (lane < 16) s_gpre[row][lane] = scan - pc;
        if (lane == 15) s_npos[row] = scan;
    }

    // --- concurrently: deferred row reduction; own-column ip to registers ---
    float4 qa = s_pp[0][tid];
    float4 qb = s_pp[1][tid];
    const float ip0 = (qa.x + qa.y) + (qa.z + qa.w);
    const float ip1 = (qb.x + qb.y) + (qb.z + qb.w);
    s_ip[0][tid] = ip0;
    s_ip[1][tid] = ip1;
    __syncthreads();                               // barrier 3

    // --- rank + compaction write (cheap: 1 LDS + popc per row) ---
    {
        const unsigned lanebits = (1u << lane) - 1u;
        if (!n0) s_poslist[0][s_gpre[0][wrp] + __popc(m0 & lanebits)] = (short)tid;
        if (!n1) s_poslist[1][s_gpre[1][wrp] + __popc(m1 & lanebits)] = (short)tid;
    }
    const int npos0 = s_npos[0];
    const int npos1 = s_npos[1];
    __syncthreads();                               // barrier 3b

    // --- inverted pair loops (clamp-free softplus; exact in data range) ---
    {
        float acc0 = 0.0f;
        for (int k = 0; k < npos0; ++k) {
            float ipp = s_ip[0][s_poslist[0][k]] - ALPHA;   // broadcast LDS
            if (n0) {
                float t = ipp - ip0;
                acc0 += __logf(1.0f + __expf(-fabsf(t))) + fmaxf(-t, 0.0f);
            }
        }
        #pragma unroll
        for (int o = 16; o > 0; o >>= 1) acc0 += __shfl_xor_sync(0xffffffffu, acc0, o);
        if (lane == 0) s_part[0][wrp] = acc0;

        float acc1 = 0.0f;
        for (int k = 0; k < npos1; ++k) {
            float ipp = s_ip[1][s_poslist[1][k]] - ALPHA;
            if (n1) {
                float t = ipp - ip1;
                acc1 += __logf(1.0f + __expf(-fabsf(t))) + fmaxf(-t, 0.0f);
            }
        }
        #pragma unroll
        for (int o = 16; o > 0; o >>= 1) acc1 += __shfl_xor_sync(0xffffffffu, acc1, o);
        if (lane == 0) s_part[1][wrp] = acc1;
    }
    __syncthreads();                               // barrier 4

    // --- block epilogue: 2 row losses + loss2 partial, publish ---
    if (tid == 0) {
        float bsum = 0.0f, bcnt = 0.0f;
        const int nposv[RPB] = {npos0, npos1};
        #pragma unroll
        for (int g = 0; g < RPB; ++g) {
            int   np = nposv[g];
            int   nn = NN - np;
            float rs = 0.0f;
            #pragma unroll
            for (int w2 = 0; w2 < 16; ++w2) rs += s_part[g][w2];
            float rl = rs / fmaxf((float)(np * nn), 1.0f);
            if (np > 0 && nn > 0) { bsum += rl; bcnt += 1.0f; }
        }
        float bl2 = s_s2[0] + s_s2[1] + s_s2[2] + s_s2[3];

        g_part[bid] = make_float4(bsum, bcnt, bl2, 0.0f);
        __threadfence();
        unsigned prev = atomicAdd(&g_done, 1u);
        s_islast = (prev == NB - 1) ? 1 : 0;
    }
    __syncthreads();                               // barrier 5

    // --- last block: warp 0 alone does the final reduction (no barriers) ---
    if (s_islast && wrp == 0) {
        float sx = 0.0f, sy = 0.0f, sz = 0.0f;
        #pragma unroll
        for (int i = 0; i < NB / 32; ++i) {        // 8 fixed-order loads/lane
            float4 v = __ldcg(&g_part[lane + 32 * i]);
            sx += v.x; sy += v.y; sz += v.z;
        }
        #pragma unroll
        for (int o = 16; o > 0; o >>= 1) {
            sx += __shfl_xor_sync(0xffffffffu, sx, o);
            sy += __shfl_xor_sync(0xffffffffu, sy, o);
            sz += __shfl_xor_sync(0xffffffffu, sz, o);
        }
        if (lane == 0) {
            float loss1 = (sy > 0.0f) ? (sx / fmaxf(sy, 1.0f)) : 0.0f;
            float loss2 = LAM * sz / (float)(NN * BIT);
            out[0] = loss1 + loss2;
            g_done = 0;   // reset for next graph replay (safe: we are last)
        }
    }
}

// ---------------------------------------------------------------------------
extern "C" void kernel_launch(void* const* d_in, const int* in_sizes, int n_in,
                              void* d_out, int out_size) {
    const float* u;
    const float* y;
    if (in_sizes[0] == NN * BIT) {
        u = (const float*)d_in[0];
        y = (const float*)d_in[1];
    } else {
        u = (const float*)d_in[1];
        y = (const float*)d_in[0];
    }
    float* out = (float*)d_out;

    fused_kernel<<<NB, NT>>>(u, y, out);
}

// round 16
// speedup vs baseline: 1.0443x; 1.0443x over previous
#include <cuda_runtime.h>
#include <math.h>

#define NN    512
#define BIT   64
#define NCLS  100
#define ALPHA 5.0f
#define LAM   1.0f
#define RPB   2                 // anchor rows per block
#define NB    (NN / RPB)        // 256 blocks
#define NT    512               // threads per block (16 warps)

// Scratch (allocation-free: __device__ globals)
__device__ float4 g_part[NB];    // {bsum, bcnt, bl2, 0} per block
__device__ unsigned int g_done = 0;

// ---------------------------------------------------------------------------
// Single fused kernel: 256 blocks x 512 threads. R16: 1-level shuffle dot
// (half-pair partials), scan-warps write the poslist (no per-thread ranking,
// one fewer barrier), merged dual-row pair loop for MUFU ILP.
// ---------------------------------------------------------------------------
__global__ void __launch_bounds__(NT) fused_kernel(const float* __restrict__ u,
                                                   const float* __restrict__ y,
                                                   float* __restrict__ out) {
    __shared__ float4 s_ur[RPB][BIT / 4];          // anchor rows of u     (512 B)
    __shared__ float  s_pp8[RPB][NN * 8];          // half-pair partials   (32 KB)
    __shared__ float  s_ip[RPB][NN];               // ip rows              (4 KB)
    __shared__ int    s_lbl[RPB];
    __shared__ unsigned s_gmask[RPB][16];          // pos bitmask words
    __shared__ int    s_npos[RPB];
    __shared__ short  s_poslist[RPB][NN];          // positive indices     (2 KB)
    __shared__ float  s_part[RPB][16];             // per-warp pair partials
    __shared__ float  s_s2[4];                     // loss2 partials
    __shared__ int    s_islast;

    const int tid  = threadIdx.x;
    const int bid  = blockIdx.x;
    const int r0   = bid * RPB;
    const int lane = tid & 31;
    const int wrp  = tid >> 5;                     // 0..15

    // --- phase 0: anchor rows of u into smem + label recovery (one-hot) ---
    if (tid < RPB * (BIT / 4)) {                   // 32 float4 loads
        int i = tid >> 4;
        int k = tid & 15;
        s_ur[i][k] = ((const float4*)(u + (size_t)(r0 + i) * BIT))[k];
    }
    if (tid < RPB * NCLS) {                        // 200 <= 512, one writer/row
        int i = tid / NCLS;
        int c = tid % NCLS;
        if (y[(size_t)(r0 + i) * NCLS + c] > 0.5f) s_lbl[i] = c;
    }
    __syncthreads();                               // barrier 1

    const int lbl0 = s_lbl[0];
    const int lbl1 = s_lbl[1];

    // --- scattered isneg gathers issued EARLY; hide under the dot loop ---
    const float yv0 = __ldg(y + (size_t)tid * NCLS + lbl0);   // row0, j = tid
    const float yv1 = __ldg(y + (size_t)tid * NCLS + lbl1);   // row1, j = tid

    // --- coalesced dot phase: 32 rows / iter, 2 anchors, 1-level shuffle ---
    {
        const float4 av0 = s_ur[0][tid & 15];
        const float4 av1 = s_ur[1][tid & 15];
        const int row_in_iter = tid >> 4;          // 0..31
        const int h = (lane & 15) >> 1;            // half-pair slot 0..7
        const bool writer = ((lane & 1) == 0);
        #pragma unroll 8
        for (int it = 0; it < NN / 32; ++it) {     // 16 iterations
            float4 b = ((const float4*)u)[it * (32 * BIT / 4) + tid];
            float p0 = av0.x * b.x + av0.y * b.y + av0.z * b.z + av0.w * b.w;
            float p1 = av1.x * b.x + av1.y * b.y + av1.z * b.z + av1.w * b.w;
            p0 += __shfl_xor_sync(0xffffffffu, p0, 1);
            p1 += __shfl_xor_sync(0xffffffffu, p1, 1);
            if (writer) {
                int row = it * 32 + row_in_iter;
                s_pp8[0][row * 8 + h] = p0;
                s_pp8[1][row * 8 + h] = p1;
            }
        }
    }

    // --- isneg in registers; ballots ---
    const bool n0 = (yv0 == 0.0f);                 // true = negative pair
    const bool n1 = (yv1 == 0.0f);
    const unsigned m0 = __ballot_sync(0xffffffffu, !n0);   // positives row0
    const unsigned m1 = __ballot_sync(0xffffffffu, !n1);   // positives row1
    if (lane == 0) {
        s_gmask[0][wrp] = m0;
        s_gmask[1][wrp] = m1;
    }

    // --- loss2 partial: this block's RPB*BIT = 128 u values (smem copy) ---
    if (tid < RPB * BIT) {
        float v  = ((const float*)s_ur)[tid];
        float sg = (v > 0.0f) ? 1.0f : ((v < 0.0f) ? -1.0f : 0.0f);
        float d  = v - sg;
        float s2 = d * d;
        #pragma unroll
        for (int o = 16; o > 0; o >>= 1) s2 += __shfl_xor_sync(0xffffffffu, s2, o);
        if (lane == 0) s_s2[wrp] = s2;
    }
    __syncthreads();                               // barrier 2

    // --- scan warps (0,1): prefix over mask-word popcounts AND write the
    //     compacted poslist directly (runs while others reduce partials) ---
    if (wrp < RPB) {
        const int row = wrp;
        unsigned word = (lane < 16) ? s_gmask[row][lane] : 0u;
        int pc = __popc(word);
        int scan = pc;
        #pragma unroll
        for (int o = 1; o < 16; o <<= 1) {
            int v = __shfl_up_sync(0xffffffffu, scan, o);
            if (lane >= o) scan += v;
        }
        if (lane == 15) s_npos[row] = scan;
        int off = scan - pc;                       // exclusive prefix
        while (word) {                             // ~0.35 bits/word avg
            int b = __ffs(word) - 1;
            s_poslist[row][off++] = (short)(lane * 32 + b);
            word &= word - 1;
        }
    }

    // --- all threads: deferred row reduction; own-column ip to registers ---
    float4 a0 = *(const float4*)&s_pp8[0][tid * 8];
    float4 a1 = *(const float4*)&s_pp8[0][tid * 8 + 4];
    float4 b0 = *(const float4*)&s_pp8[1][tid * 8];
    float4 b1 = *(const float4*)&s_pp8[1][tid * 8 + 4];
    const float ip0 = ((a0.x + a0.y) + (a0.z + a0.w)) + ((a1.x + a1.y) + (a1.z + a1.w));
    const float ip1 = ((b0.x + b0.y) + (b0.z + b0.w)) + ((b1.x + b1.y) + (b1.z + b1.w));
    s_ip[0][tid] = ip0;
    s_ip[1][tid] = ip1;
    __syncthreads();                               // barrier 3

    const int npos0 = s_npos[0];
    const int npos1 = s_npos[1];

    // --- merged pair loop: both rows in one loop (2 independent MUFU chains) ---
    {
        float acc0 = 0.0f;
        float acc1 = 0.0f;
        const int kmax = (npos0 > npos1) ? npos0 : npos1;
        for (int k = 0; k < kmax; ++k) {
            if (n0 && k < npos0) {
                float t = (s_ip[0][s_poslist[0][k]] - ALPHA) - ip0;
                acc0 += __logf(1.0f + __expf(-fabsf(t))) + fmaxf(-t, 0.0f);
            }
            if (n1 && k < npos1) {
                float t = (s_ip[1][s_poslist[1][k]] - ALPHA) - ip1;
                acc1 += __logf(1.0f + __expf(-fabsf(t))) + fmaxf(-t, 0.0f);
            }
        }
        #pragma unroll
        for (int o = 16; o > 0; o >>= 1) {
            acc0 += __shfl_xor_sync(0xffffffffu, acc0, o);
            acc1 += __shfl_xor_sync(0xffffffffu, acc1, o);
        }
        if (lane == 0) {
            s_part[0][wrp] = acc0;
            s_part[1][wrp] = acc1;
        }
    }
    __syncthreads();                               // barrier 4

    // --- block epilogue: 2 row losses + loss2 partial, publish ---
    if (tid == 0) {
        float bsum = 0.0f, bcnt = 0.0f;
        const int nposv[RPB] = {npos0, npos1};
        #pragma unroll
        for (int g = 0; g < RPB; ++g) {
            int   np = nposv[g];
            int   nn = NN - np;
            float rs = 0.0f;
            #pragma unroll
            for (int w2 = 0; w2 < 16; ++w2) rs += s_part[g][w2];
            float rl = rs / fmaxf((float)(np * nn), 1.0f);
            if (np > 0 && nn > 0) { bsum += rl; bcnt += 1.0f; }
        }
        float bl2 = s_s2[0] + s_s2[1] + s_s2[2] + s_s2[3];

        g_part[bid] = make_float4(bsum, bcnt, bl2, 0.0f);
        __threadfence();
        unsigned prev = atomicAdd(&g_done, 1u);
        s_islast = (prev == NB - 1) ? 1 : 0;
    }
    __syncthreads();                               // barrier 5

    // --- last block: warp 0 alone does the final reduction (no barriers) ---
    if (s_islast && wrp == 0) {
        float sx = 0.0f, sy = 0.0f, sz = 0.0f;
        #pragma unroll
        for (int i = 0; i < NB / 32; ++i) {        // 8 fixed-order loads/lane
            float4 v = __ldcg(&g_part[lane + 32 * i]);
            sx += v.x; sy += v.y; sz += v.z;
        }
        #pragma unroll
        for (int o = 16; o > 0; o >>= 1) {
            sx += __shfl_xor_sync(0xffffffffu, sx, o);
            sy += __shfl_xor_sync(0xffffffffu, sy, o);
            sz += __shfl_xor_sync(0xffffffffu, sz, o);
        }
        if (lane == 0) {
            float loss1 = (sy > 0.0f) ? (sx / fmaxf(sy, 1.0f)) : 0.0f;
            float loss2 = LAM * sz / (float)(NN * BIT);
            out[0] = loss1 + loss2;
            g_done = 0;   // reset for next graph replay (safe: we are last)
        }
    }
}

// ---------------------------------------------------------------------------
extern "C" void kernel_launch(void* const* d_in, const int* in_sizes, int n_in,
                              void* d_out, int out_size) {
    const float* u;
    const float* y;
    if (in_sizes[0] == NN * BIT) {
        u = (const float*)d_in[0];
        y = (const float*)d_in[1];
    } else {
        u = (const float*)d_in[1];
        y = (const float*)d_in[0];
    }
    float* out = (float*)d_out;

    fused_kernel<<<NB, NT>>>(u, y, out);
}

// round 17
// speedup vs baseline: 1.0803x; 1.0344x over previous
#include <cuda_runtime.h>
#include <math.h>

#define NN    512
#define BIT   64
#define NCLS  100
#define ALPHA 5.0f
#define LAM   1.0f
#define RPB   2                 // anchor rows per block
#define NB    (NN / RPB)        // 256 blocks
#define NT    512               // threads per block (16 warps)

// Scratch (allocation-free: __device__ globals)
__device__ float4 g_part[NB];    // {bsum, bcnt, bl2, 0} per block
__device__ unsigned int g_done = 0;

// ---------------------------------------------------------------------------
// Single fused kernel: 256 blocks x 512 threads. R17: product-form softplus --
// sum(log1p(w_k)) = log(prod(1+w_k)) -- halves MUFU ops (the measured
// bottleneck pipe); one __logf per row per thread instead of one per eval.
// ---------------------------------------------------------------------------
__global__ void __launch_bounds__(NT) fused_kernel(const float* __restrict__ u,
                                                   const float* __restrict__ y,
                                                   float* __restrict__ out) {
    __shared__ float4 s_ur[RPB][BIT / 4];          // anchor rows of u     (512 B)
    __shared__ float  s_pp8[RPB][NN * 8];          // half-pair partials   (32 KB)
    __shared__ float  s_ip[RPB][NN];               // ip rows              (4 KB)
    __shared__ int    s_lbl[RPB];
    __shared__ unsigned s_gmask[RPB][16];          // pos bitmask words
    __shared__ int    s_npos[RPB];
    __shared__ short  s_poslist[RPB][NN];          // positive indices     (2 KB)
    __shared__ float  s_part[RPB][16];             // per-warp pair partials
    __shared__ float  s_s2[4];                     // loss2 partials
    __shared__ int    s_islast;

    const int tid  = threadIdx.x;
    const int bid  = blockIdx.x;
    const int r0   = bid * RPB;
    const int lane = tid & 31;
    const int wrp  = tid >> 5;                     // 0..15

    // --- phase 0: anchor rows of u into smem + label recovery (one-hot) ---
    if (tid < RPB * (BIT / 4)) {                   // 32 float4 loads
        int i = tid >> 4;
        int k = tid & 15;
        s_ur[i][k] = ((const float4*)(u + (size_t)(r0 + i) * BIT))[k];
    }
    if (tid < RPB * NCLS) {                        // 200 <= 512, one writer/row
        int i = tid / NCLS;
        int c = tid % NCLS;
        if (y[(size_t)(r0 + i) * NCLS + c] > 0.5f) s_lbl[i] = c;
    }
    __syncthreads();                               // barrier 1

    const int lbl0 = s_lbl[0];
    const int lbl1 = s_lbl[1];

    // --- scattered isneg gathers issued EARLY; hide under the dot loop ---
    const float yv0 = __ldg(y + (size_t)tid * NCLS + lbl0);   // row0, j = tid
    const float yv1 = __ldg(y + (size_t)tid * NCLS + lbl1);   // row1, j = tid

    // --- coalesced dot phase: 32 rows / iter, 2 anchors, 1-level shuffle ---
    {
        const float4 av0 = s_ur[0][tid & 15];
        const float4 av1 = s_ur[1][tid & 15];
        const int row_in_iter = tid >> 4;          // 0..31
        const int h = (lane & 15) >> 1;            // half-pair slot 0..7
        const bool writer = ((lane & 1) == 0);
        #pragma unroll 8
        for (int it = 0; it < NN / 32; ++it) {     // 16 iterations
            float4 b = ((const float4*)u)[it * (32 * BIT / 4) + tid];
            float p0 = av0.x * b.x + av0.y * b.y + av0.z * b.z + av0.w * b.w;
            float p1 = av1.x * b.x + av1.y * b.y + av1.z * b.z + av1.w * b.w;
            p0 += __shfl_xor_sync(0xffffffffu, p0, 1);
            p1 += __shfl_xor_sync(0xffffffffu, p1, 1);
            if (writer) {
                int row = it * 32 + row_in_iter;
                s_pp8[0][row * 8 + h] = p0;
                s_pp8[1][row * 8 + h] = p1;
            }
        }
    }

    // --- isneg in registers; ballots ---
    const bool n0 = (yv0 == 0.0f);                 // true = negative pair
    const bool n1 = (yv1 == 0.0f);
    const unsigned m0 = __ballot_sync(0xffffffffu, !n0);   // positives row0
    const unsigned m1 = __ballot_sync(0xffffffffu, !n1);   // positives row1
    if (lane == 0) {
        s_gmask[0][wrp] = m0;
        s_gmask[1][wrp] = m1;
    }

    // --- loss2 partial: this block's RPB*BIT = 128 u values (smem copy) ---
    if (tid < RPB * BIT) {
        float v  = ((const float*)s_ur)[tid];
        float sg = (v > 0.0f) ? 1.0f : ((v < 0.0f) ? -1.0f : 0.0f);
        float d  = v - sg;
        float s2 = d * d;
        #pragma unroll
        for (int o = 16; o > 0; o >>= 1) s2 += __shfl_xor_sync(0xffffffffu, s2, o);
        if (lane == 0) s_s2[wrp] = s2;
    }
    __syncthreads();                               // barrier 2

    // --- scan warps (0,1): prefix over mask-word popcounts AND write the
    //     compacted poslist directly (runs while others reduce partials) ---
    if (wrp < RPB) {
        const int row = wrp;
        unsigned word = (lane < 16) ? s_gmask[row][lane] : 0u;
        int pc = __popc(word);
        int scan = pc;
        #pragma unroll
        for (int o = 1; o < 16; o <<= 1) {
            int v = __shfl_up_sync(0xffffffffu, scan, o);
            if (lane >= o) scan += v;
        }
        if (lane == 15) s_npos[row] = scan;
        int off = scan - pc;                       // exclusive prefix
        while (word) {                             // ~0.35 bits/word avg
            int b = __ffs(word) - 1;
            s_poslist[row][off++] = (short)(lane * 32 + b);
            word &= word - 1;
        }
    }

    // --- all threads: deferred row reduction; own-column ip to registers ---
    float4 a0 = *(const float4*)&s_pp8[0][tid * 8];
    float4 a1 = *(const float4*)&s_pp8[0][tid * 8 + 4];
    float4 b0 = *(const float4*)&s_pp8[1][tid * 8];
    float4 b1 = *(const float4*)&s_pp8[1][tid * 8 + 4];
    const float ip0 = ((a0.x + a0.y) + (a0.z + a0.w)) + ((a1.x + a1.y) + (a1.z + a1.w));
    const float ip1 = ((b0.x + b0.y) + (b0.z + b0.w)) + ((b1.x + b1.y) + (b1.z + b1.w));
    s_ip[0][tid] = ip0;
    s_ip[1][tid] = ip1;
    __syncthreads();                               // barrier 3

    const int npos0 = s_npos[0];
    const int npos1 = s_npos[1];

    // --- merged pair loop, product-form softplus:
    //     f = log1p(exp(-|t|)) + max(-t,0);  sum of log1p terms taken as a
    //     single log of the product (1 MUFU per eval instead of 2) ---
    {
        float acc0 = 0.0f, acc1 = 0.0f;
        float P0 = 1.0f,   P1 = 1.0f;
        const float base0 = ip0 + ALPHA;           // t = ipp - base
        const float base1 = ip1 + ALPHA;
        const int kmax = (npos0 > npos1) ? npos0 : npos1;
        for (int k = 0; k < kmax; ++k) {
            if (n0 && k < npos0) {
                float t = s_ip[0][s_poslist[0][k]] - base0;
                acc0 += fmaxf(-t, 0.0f);
                P0 *= 1.0f + __expf(-fabsf(t));
            }
            if (n1 && k < npos1) {
                float t = s_ip[1][s_poslist[1][k]] - base1;
                acc1 += fmaxf(-t, 0.0f);
                P1 *= 1.0f + __expf(-fabsf(t));
            }
        }
        acc0 += __logf(P0);                        // one log per row per thread
        acc1 += __logf(P1);
        #pragma unroll
        for (int o = 16; o > 0; o >>= 1) {
            acc0 += __shfl_xor_sync(0xffffffffu, acc0, o);
            acc1 += __shfl_xor_sync(0xffffffffu, acc1, o);
        }
        if (lane == 0) {
            s_part[0][wrp] = acc0;
            s_part[1][wrp] = acc1;
        }
    }
    __syncthreads();                               // barrier 4

    // --- block epilogue: 2 row losses + loss2 partial, publish ---
    if (tid == 0) {
        float bsum = 0.0f, bcnt = 0.0f;
        const int nposv[RPB] = {npos0, npos1};
        #pragma unroll
        for (int g = 0; g < RPB; ++g) {
            int   np = nposv[g];
            int   nn = NN - np;
            float rs = 0.0f;
            #pragma unroll
            for (int w2 = 0; w2 < 16; ++w2) rs += s_part[g][w2];
            float rl = rs / fmaxf((float)(np * nn), 1.0f);
            if (np > 0 && nn > 0) { bsum += rl; bcnt += 1.0f; }
        }
        float bl2 = s_s2[0] + s_s2[1] + s_s2[2] + s_s2[3];

        g_part[bid] = make_float4(bsum, bcnt, bl2, 0.0f);
        __threadfence();
        unsigned prev = atomicAdd(&g_done, 1u);
        s_islast = (prev == NB - 1) ? 1 : 0;
    }
    __syncthreads();                               // barrier 5

    // --- last block: warp 0 alone does the final reduction (no barriers) ---
    if (s_islast && wrp == 0) {
        float sx = 0.0f, sy = 0.0f, sz = 0.0f;
        #pragma unroll
        for (int i = 0; i < NB / 32; ++i) {        // 8 fixed-order loads/lane
            float4 v = __ldcg(&g_part[lane + 32 * i]);
            sx += v.x; sy += v.y; sz += v.z;
        }
        #pragma unroll
        for (int o = 16; o > 0; o >>= 1) {
            sx += __shfl_xor_sync(0xffffffffu, sx, o);
            sy += __shfl_xor_sync(0xffffffffu, sy, o);
            sz += __shfl_xor_sync(0xffffffffu, sz, o);
        }
        if (lane == 0) {
            float loss1 = (sy > 0.0f) ? (sx / fmaxf(sy, 1.0f)) : 0.0f;
            float loss2 = LAM * sz / (float)(NN * BIT);
            out[0] = loss1 + loss2;
            g_done = 0;   // reset for next graph replay (safe: we are last)
        }
    }
}

// ---------------------------------------------------------------------------
extern "C" void kernel_launch(void* const* d_in, const int* in_sizes, int n_in,
                              void* d_out, int out_size) {
    const float* u;
    const float* y;
    if (in_sizes[0] == NN * BIT) {
        u = (const float*)d_in[0];
        y = (const float*)d_in[1];
    } else {
        u = (const float*)d_in[1];
        y = (const float*)d_in[0];
    }
    float* out = (float*)d_out;

    fused_kernel<<<NB, NT>>>(u, y, out);
}